// round 2
// baseline (speedup 1.0000x reference)
#include <cuda_runtime.h>

#define NN 50000
#define EE 800000
#define IND 128
#define HD 64
#define TOTE (EE + NN)

// ---------------- scratch (static device memory; no allocations) ----------------
__device__ __align__(256) float d_h[NN * HD];
__device__ __align__(256) float d_x1[NN * HD];
__device__ __align__(256) float d_x2[NN * HD];
__device__ __align__(256) float d_accum[NN * HD];
__device__ __align__(256) float d_proj[NN * HD];
__device__ __align__(256) float d_as[NN];
__device__ __align__(256) float d_ad[NN];
__device__ __align__(256) float d_denom[NN];
__device__ __align__(256) unsigned d_emax[NN];
__device__ __align__(256) float d_gsum[HD];

// ordered-uint mapping for float atomicMax (monotone)
__device__ __forceinline__ unsigned f2o(float f) {
    unsigned u = __float_as_uint(f);
    return (u & 0x80000000u) ? ~u : (u | 0x80000000u);
}
__device__ __forceinline__ float o2f(unsigned u) {
    return (u & 0x80000000u) ? __uint_as_float(u ^ 0x80000000u)
                             : __uint_as_float(~u);
}

// ---------------- GEMM: Y[n, 0:64] = X[n, 0:K] @ W[K, 64] ----------------
// block = 256 threads, 16 nodes per block; W and X tile staged in shared.
template <int K>
__global__ void __launch_bounds__(256) gemm16(const float* __restrict__ X,
                                              const float* __restrict__ W,
                                              float* __restrict__ Y) {
    __shared__ float Ws[K * HD];
    __shared__ float Xs[16 * K];
    int t = threadIdx.x;
    for (int i = t; i < K * HD; i += 256) Ws[i] = W[i];
    int nb = blockIdx.x * 16;
    for (int i = t; i < 16 * K; i += 256) {
        int r = i / K, c = i - r * K;
        int node = nb + r;
        Xs[i] = (node < NN) ? X[(size_t)node * K + c] : 0.f;
    }
    __syncthreads();
    int col = t & 63, g = t >> 6;
    float a0 = 0.f, a1 = 0.f, a2 = 0.f, a3 = 0.f;
#pragma unroll 8
    for (int k = 0; k < K; k++) {
        float w = Ws[k * HD + col];
        a0 += Xs[(g * 4 + 0) * K + k] * w;
        a1 += Xs[(g * 4 + 1) * K + k] * w;
        a2 += Xs[(g * 4 + 2) * K + k] * w;
        a3 += Xs[(g * 4 + 3) * K + k] * w;
    }
    int n0 = nb + g * 4;
    if (n0 + 0 < NN) Y[(size_t)(n0 + 0) * HD + col] = a0;
    if (n0 + 1 < NN) Y[(size_t)(n0 + 1) * HD + col] = a1;
    if (n0 + 2 < NN) Y[(size_t)(n0 + 2) * HD + col] = a2;
    if (n0 + 3 < NN) Y[(size_t)(n0 + 3) * HD + col] = a3;
}

// ---------------- per-node attention scores: as[n]=h[n].a_s, ad[n]=h[n].a_d ----
__global__ void __launch_bounds__(256) attn_scores(const float* __restrict__ h,
                                                   const float* __restrict__ a_s,
                                                   const float* __restrict__ a_d,
                                                   float* __restrict__ as_o,
                                                   float* __restrict__ ad_o) {
    int warp = (blockIdx.x * blockDim.x + threadIdx.x) >> 5;
    int lane = threadIdx.x & 31;
    if (warp >= NN) return;
    float h0 = h[(size_t)warp * HD + lane];
    float h1 = h[(size_t)warp * HD + 32 + lane];
    float s = h0 * a_s[lane] + h1 * a_s[32 + lane];
    float d = h0 * a_d[lane] + h1 * a_d[32 + lane];
#pragma unroll
    for (int o = 16; o; o >>= 1) {
        s += __shfl_xor_sync(0xffffffffu, s, o);
        d += __shfl_xor_sync(0xffffffffu, d, o);
    }
    if (lane == 0) { as_o[warp] = s; ad_o[warp] = d; }
}

// ---------------- init per-layer segment buffers ----------------
__global__ void __launch_bounds__(256) init_seg(float* __restrict__ accum,
                                                float* __restrict__ denom,
                                                unsigned* __restrict__ emax) {
    int i = blockIdx.x * blockDim.x + threadIdx.x;
    if (i < NN * HD) accum[i] = 0.f;
    if (i < NN) { denom[i] = 0.f; emax[i] = 0x007FFFFFu; /* f2o(-inf) */ }
}

// ---------------- edge pass 1: segment max ----------------
__global__ void __launch_bounds__(256) edge_max(const int* __restrict__ src,
                                                const int* __restrict__ dst,
                                                const float* __restrict__ as_,
                                                const float* __restrict__ ad_,
                                                unsigned* __restrict__ emax) {
    int i = blockIdx.x * blockDim.x + threadIdx.x;
    if (i >= TOTE) return;
    int s, d;
    if (i < EE) { s = src[i]; d = dst[i]; } else { s = d = i - EE; }
    float e = as_[s] + ad_[d];
    e = e > 0.f ? e : 0.2f * e;
    atomicMax(&emax[d], f2o(e));
}

// ---------------- edge pass 2: denom += ex ; accum[dst] += ex*h[src] ----------
// 16 threads per edge; each thread handles float4 (4 cols) via red.v4.f32
__global__ void __launch_bounds__(256) edge_agg(const int* __restrict__ src,
                                                const int* __restrict__ dst,
                                                const float* __restrict__ as_,
                                                const float* __restrict__ ad_,
                                                const unsigned* __restrict__ emax,
                                                const float* __restrict__ h,
                                                float* __restrict__ denom,
                                                float* __restrict__ accum) {
    unsigned tid = blockIdx.x * blockDim.x + threadIdx.x;
    unsigned i = tid >> 4;
    unsigned q = tid & 15;
    if (i >= TOTE) return;
    int s, d;
    if (i < EE) { s = src[i]; d = dst[i]; } else { s = d = i - EE; }
    float e = as_[s] + ad_[d];
    e = e > 0.f ? e : 0.2f * e;
    float ex = __expf(e - o2f(emax[d]));
    if (q == 0) atomicAdd(&denom[d], ex);
    float4 hv = reinterpret_cast<const float4*>(h)[(size_t)s * 16 + q];
    float* p = accum + (size_t)d * HD + q * 4;
    asm volatile("red.global.add.v4.f32 [%0], {%1,%2,%3,%4};" ::"l"(p),
                 "f"(ex * hv.x), "f"(ex * hv.y), "f"(ex * hv.z), "f"(ex * hv.w)
                 : "memory");
}

// ---------------- node post, layer 1: relu + bn ----------------
__global__ void __launch_bounds__(256) post1(const float* __restrict__ accum,
                                             const float* __restrict__ denom,
                                             const float* __restrict__ b,
                                             const float* __restrict__ bg,
                                             const float* __restrict__ bb,
                                             const float* __restrict__ bm,
                                             const float* __restrict__ bv,
                                             float* __restrict__ xp) {
    int i = blockIdx.x * blockDim.x + threadIdx.x;
    if (i >= NN * HD) return;
    int c = i & 63, n = i >> 6;
    float v = accum[i] / (denom[n] + 1e-16f) + b[c];
    v = fmaxf(v, 0.f);
    v = (v - bm[c]) * rsqrtf(bv[c] + 1e-5f) * bg[c] + bb[c];
    xp[i] = v;
}

// ---------------- node post, layers 2..5: relu + bn + residual proj ----------
__global__ void __launch_bounds__(256) post2(const float* __restrict__ accum,
                                             const float* __restrict__ denom,
                                             const float* __restrict__ b,
                                             const float* __restrict__ bg,
                                             const float* __restrict__ bb,
                                             const float* __restrict__ bm,
                                             const float* __restrict__ bv,
                                             const float* __restrict__ proj,
                                             const float* __restrict__ projb,
                                             float* __restrict__ xn) {
    int i = blockIdx.x * blockDim.x + threadIdx.x;
    if (i >= NN * HD) return;
    int c = i & 63, n = i >> 6;
    float v = accum[i] / (denom[n] + 1e-16f) + b[c];
    v = fmaxf(v, 0.f);
    v = (v - bm[c]) * rsqrtf(bv[c] + 1e-5f) * bg[c] + bb[c];
    xn[i] = v + proj[i] + projb[c];
}

// ---------------- mean pool ----------------
__global__ void zero_gsum(float* __restrict__ g) {
    if (threadIdx.x < HD) g[threadIdx.x] = 0.f;
}
__global__ void __launch_bounds__(256) pool(const float* __restrict__ xp,
                                            float* __restrict__ gsum) {
    int t = threadIdx.x;
    int c = t & 63;
    int row0 = blockIdx.x * 4 + (t >> 6);
    float acc = 0.f;
    for (int n = row0; n < NN; n += gridDim.x * 4) acc += xp[(size_t)n * HD + c];
    atomicAdd(&gsum[c], acc);
}

// ---------------- head MLP ----------------
__global__ void head(const float* __restrict__ gsum, const float* __restrict__ hW1,
                     const float* __restrict__ hb1, const float* __restrict__ hg,
                     const float* __restrict__ hb, const float* __restrict__ hm,
                     const float* __restrict__ hv, const float* __restrict__ hW2,
                     const float* __restrict__ hb2, float* __restrict__ out) {
    __shared__ float g[HD];
    int t = threadIdx.x;
    if (t < HD) g[t] = gsum[t] * (1.f / NN);
    __syncthreads();
    float r = 0.f;
    if (t < 32) {
        float acc = hb1[t];
#pragma unroll
        for (int k = 0; k < HD; k++) acc += g[k] * hW1[k * 32 + t];
        acc = fmaxf(acc, 0.f);
        acc = (acc - hm[t]) * rsqrtf(hv[t] + 1e-5f) * hg[t] + hb[t];
        r = acc * hW2[t];
#pragma unroll
        for (int o = 16; o; o >>= 1) r += __shfl_xor_sync(0xffffffffu, r, o);
        if (t == 0) out[0] = r + hb2[0];
    }
}

// ---------------- launch ----------------
extern "C" void kernel_launch(void* const* d_in, const int* in_sizes, int n_in,
                              void* d_out, int out_size) {
    (void)in_sizes; (void)n_in; (void)out_size;
    const float* x        = (const float*)d_in[0];
    const int*   ei       = (const int*)d_in[1];
    const float* conv1_W  = (const float*)d_in[2];
    const float* conv1_as = (const float*)d_in[3];
    const float* conv1_ad = (const float*)d_in[4];
    const float* conv1_b  = (const float*)d_in[5];
    const float* convW    = (const float*)d_in[6];
    const float* conv_as  = (const float*)d_in[7];
    const float* conv_ad  = (const float*)d_in[8];
    const float* conv_b   = (const float*)d_in[9];
    const float* bn_g     = (const float*)d_in[10];
    const float* bn_b     = (const float*)d_in[11];
    const float* bn_m     = (const float*)d_in[12];
    const float* bn_v     = (const float*)d_in[13];
    const float* projW    = (const float*)d_in[14];
    const float* projb    = (const float*)d_in[15];
    const float* hW1      = (const float*)d_in[16];
    const float* hb1      = (const float*)d_in[17];
    const float* hbn_g    = (const float*)d_in[18];
    const float* hbn_b    = (const float*)d_in[19];
    const float* hbn_m    = (const float*)d_in[20];
    const float* hbn_v    = (const float*)d_in[21];
    const float* hW2      = (const float*)d_in[22];
    const float* hb2      = (const float*)d_in[23];

    const int* src = ei;
    const int* dst = ei + EE;

    float *h, *x1, *x2, *accum, *proj, *as_, *ad_, *denom, *gsum;
    unsigned* emax;
    cudaGetSymbolAddress((void**)&h, d_h);
    cudaGetSymbolAddress((void**)&x1, d_x1);
    cudaGetSymbolAddress((void**)&x2, d_x2);
    cudaGetSymbolAddress((void**)&accum, d_accum);
    cudaGetSymbolAddress((void**)&proj, d_proj);
    cudaGetSymbolAddress((void**)&as_, d_as);
    cudaGetSymbolAddress((void**)&ad_, d_ad);
    cudaGetSymbolAddress((void**)&denom, d_denom);
    cudaGetSymbolAddress((void**)&emax, d_emax);
    cudaGetSymbolAddress((void**)&gsum, d_gsum);

    const int GB = (NN + 15) / 16;                  // gemm blocks
    const int AB = (NN * 32 + 255) / 256;           // attn_scores blocks
    const int IB = (NN * HD + 255) / 256;           // init / post blocks
    const int MB = (TOTE + 255) / 256;              // edge_max blocks
    const int EB = ((long long)TOTE * 16 + 255) / 256;  // edge_agg blocks

    // ---- layer 1 ----
    gemm16<IND><<<GB, 256>>>(x, conv1_W, h);
    attn_scores<<<AB, 256>>>(h, conv1_as, conv1_ad, as_, ad_);
    init_seg<<<IB, 256>>>(accum, denom, emax);
    edge_max<<<MB, 256>>>(src, dst, as_, ad_, emax);
    edge_agg<<<EB, 256>>>(src, dst, as_, ad_, emax, h, denom, accum);
    post1<<<IB, 256>>>(accum, denom, conv1_b, bn_g, bn_b, bn_m, bn_v, x1);

    float* xp = x1;
    float* xn = x2;
    for (int l = 0; l < 4; l++) {
        gemm16<HD><<<GB, 256>>>(xp, convW + l * HD * HD, h);
        gemm16<HD><<<GB, 256>>>(xp, projW + l * HD * HD, proj);
        attn_scores<<<AB, 256>>>(h, conv_as + l * HD, conv_ad + l * HD, as_, ad_);
        init_seg<<<IB, 256>>>(accum, denom, emax);
        edge_max<<<MB, 256>>>(src, dst, as_, ad_, emax);
        edge_agg<<<EB, 256>>>(src, dst, as_, ad_, emax, h, denom, accum);
        post2<<<IB, 256>>>(accum, denom, conv_b + l * HD, bn_g + (l + 1) * HD,
                           bn_b + (l + 1) * HD, bn_m + (l + 1) * HD,
                           bn_v + (l + 1) * HD, proj, projb + l * HD, xn);
        float* tmp = xp; xp = xn; xn = tmp;
    }

    zero_gsum<<<1, 64>>>(gsum);
    pool<<<256, 256>>>(xp, gsum);
    head<<<1, 64>>>(gsum, hW1, hb1, hbn_g, hbn_b, hbn_m, hbn_v, hW2, hb2,
                    (float*)d_out);
}

// round 5
// speedup vs baseline: 2.1468x; 2.1468x over previous
#include <cuda_runtime.h>

#define NN 50000
#define EE 800000
#define IND 128
#define HD 64
#define TOTE (EE + NN)
#define NB_SCAN 196   // ceil(NN/256)

// ---------------- scratch (static device memory; no allocations) ----------------
__device__ __align__(256) float d_h[NN * HD];
__device__ __align__(256) float d_x1[NN * HD];
__device__ __align__(256) float d_x2[NN * HD];
__device__ __align__(256) float d_proj[NN * HD];
__device__ __align__(256) float d_as[NN];
__device__ __align__(256) float d_ad[NN];
__device__ __align__(256) float d_gsum[HD];
__device__ __align__(256) int   d_cnt[NN];
__device__ __align__(256) int   d_roff[NN];
__device__ __align__(256) int   d_fill[NN];
__device__ __align__(256) int   d_bsum[NB_SCAN];
__device__ __align__(256) int   d_esrc[TOTE];

// ---------------- CSR build ----------------
__global__ void __launch_bounds__(256) zero_cf(int* __restrict__ cnt,
                                               int* __restrict__ fill) {
    int i = blockIdx.x * blockDim.x + threadIdx.x;
    if (i < NN) { cnt[i] = 0; fill[i] = 0; }
}

__global__ void __launch_bounds__(256) hist(const int* __restrict__ dst,
                                            int* __restrict__ cnt) {
    int i = blockIdx.x * blockDim.x + threadIdx.x;
    if (i >= TOTE) return;
    int d = (i < EE) ? dst[i] : (i - EE);
    atomicAdd(&cnt[d], 1);
}

__global__ void __launch_bounds__(256) scan1(const int* __restrict__ cnt,
                                             int* __restrict__ roff,
                                             int* __restrict__ bsum) {
    __shared__ int sh[256];
    int t = threadIdx.x;
    int i = blockIdx.x * 256 + t;
    int v = (i < NN) ? cnt[i] : 0;
    sh[t] = v;
    __syncthreads();
#pragma unroll
    for (int o = 1; o < 256; o <<= 1) {
        int u = (t >= o) ? sh[t - o] : 0;
        __syncthreads();
        sh[t] += u;
        __syncthreads();
    }
    if (i < NN) roff[i] = sh[t] - v;           // exclusive
    if (t == 255) bsum[blockIdx.x] = sh[255];  // block total
}

__global__ void __launch_bounds__(256) scan2(int* __restrict__ bsum) {
    __shared__ int sh[256];
    int t = threadIdx.x;
    int v = (t < NB_SCAN) ? bsum[t] : 0;
    sh[t] = v;
    __syncthreads();
#pragma unroll
    for (int o = 1; o < 256; o <<= 1) {
        int u = (t >= o) ? sh[t - o] : 0;
        __syncthreads();
        sh[t] += u;
        __syncthreads();
    }
    if (t < NB_SCAN) bsum[t] = sh[t] - v;      // exclusive over blocks
}

__global__ void __launch_bounds__(256) scan3(int* __restrict__ roff,
                                             const int* __restrict__ bsum) {
    int i = blockIdx.x * blockDim.x + threadIdx.x;
    if (i < NN) roff[i] += bsum[i >> 8];
}

__global__ void __launch_bounds__(256) scatter(const int* __restrict__ src,
                                               const int* __restrict__ dst,
                                               const int* __restrict__ roff,
                                               int* __restrict__ fill,
                                               int* __restrict__ esrc) {
    int i = blockIdx.x * blockDim.x + threadIdx.x;
    if (i >= TOTE) return;
    int s, d;
    if (i < EE) { s = src[i]; d = dst[i]; } else { s = d = i - EE; }
    int pos = roff[d] + atomicAdd(&fill[d], 1);
    esrc[pos] = s;
}

// ---------------- GEMM + fused attention scores ----------------
// Y[n, 0:64] = X[n, 0:K] @ W[K, 64]; also as_o[n]=Y[n].a_s, ad_o[n]=Y[n].a_d
// block = 256 threads, 16 nodes per block.
template <int K>
__global__ void __launch_bounds__(256) gemm16(const float* __restrict__ X,
                                              const float* __restrict__ W,
                                              float* __restrict__ Y,
                                              const float* __restrict__ a_s,
                                              const float* __restrict__ a_d,
                                              float* __restrict__ as_o,
                                              float* __restrict__ ad_o) {
    __shared__ float Ws[K * HD];
    __shared__ float Xs[16 * K];
    __shared__ float Ssh[16], Dsh[16];
    int t = threadIdx.x;
    for (int i = t; i < K * HD; i += 256) Ws[i] = W[i];
    int nb = blockIdx.x * 16;
    for (int i = t; i < 16 * K; i += 256) {
        int r = i / K, c = i - r * K;
        int node = nb + r;
        Xs[i] = (node < NN) ? X[(size_t)node * K + c] : 0.f;
    }
    if (as_o && t < 16) { Ssh[t] = 0.f; Dsh[t] = 0.f; }
    __syncthreads();
    int col = t & 63, g = t >> 6;
    float a0 = 0.f, a1 = 0.f, a2 = 0.f, a3 = 0.f;
#pragma unroll 8
    for (int k = 0; k < K; k++) {
        float w = Ws[k * HD + col];
        a0 += Xs[(g * 4 + 0) * K + k] * w;
        a1 += Xs[(g * 4 + 1) * K + k] * w;
        a2 += Xs[(g * 4 + 2) * K + k] * w;
        a3 += Xs[(g * 4 + 3) * K + k] * w;
    }
    int n0 = nb + g * 4;
    if (n0 + 0 < NN) Y[(size_t)(n0 + 0) * HD + col] = a0;
    if (n0 + 1 < NN) Y[(size_t)(n0 + 1) * HD + col] = a1;
    if (n0 + 2 < NN) Y[(size_t)(n0 + 2) * HD + col] = a2;
    if (n0 + 3 < NN) Y[(size_t)(n0 + 3) * HD + col] = a3;
    if (as_o) {
        float sv = a_s[col], dv = a_d[col];
        // partial within warp: lanes hold distinct cols of the same 4 rows
        float s0 = a0 * sv, s1 = a1 * sv, s2 = a2 * sv, s3 = a3 * sv;
        float d0 = a0 * dv, d1 = a1 * dv, d2 = a2 * dv, d3 = a3 * dv;
#pragma unroll
        for (int o = 16; o; o >>= 1) {
            s0 += __shfl_xor_sync(0xffffffffu, s0, o);
            s1 += __shfl_xor_sync(0xffffffffu, s1, o);
            s2 += __shfl_xor_sync(0xffffffffu, s2, o);
            s3 += __shfl_xor_sync(0xffffffffu, s3, o);
            d0 += __shfl_xor_sync(0xffffffffu, d0, o);
            d1 += __shfl_xor_sync(0xffffffffu, d1, o);
            d2 += __shfl_xor_sync(0xffffffffu, d2, o);
            d3 += __shfl_xor_sync(0xffffffffu, d3, o);
        }
        if ((t & 31) == 0) {  // one lane per warp; 2 warps contribute per row grp
            atomicAdd(&Ssh[g * 4 + 0], s0);
            atomicAdd(&Ssh[g * 4 + 1], s1);
            atomicAdd(&Ssh[g * 4 + 2], s2);
            atomicAdd(&Ssh[g * 4 + 3], s3);
            atomicAdd(&Dsh[g * 4 + 0], d0);
            atomicAdd(&Dsh[g * 4 + 1], d1);
            atomicAdd(&Dsh[g * 4 + 2], d2);
            atomicAdd(&Dsh[g * 4 + 3], d3);
        }
        __syncthreads();
        if (t < 16 && nb + t < NN) {
            as_o[nb + t] = Ssh[t];
            ad_o[nb + t] = Dsh[t];
        }
    }
}

// ---------------- fused gather-aggregate + softmax + bias/relu/bn(+proj) ------
// One warp per destination node. Lane covers cols [2*lane, 2*lane+1] (float2).
template <bool PROJ>
__global__ void __launch_bounds__(256) agg_post(
    const int* __restrict__ roff, const int* __restrict__ cnt,
    const int* __restrict__ esrc, const float* __restrict__ as_,
    const float* __restrict__ ad_, const float* __restrict__ h,
    const float* __restrict__ bias, const float* __restrict__ bg,
    const float* __restrict__ bb, const float* __restrict__ bm,
    const float* __restrict__ bv, const float* __restrict__ proj,
    const float* __restrict__ projb, float* __restrict__ out) {
    int node = (blockIdx.x * blockDim.x + threadIdx.x) >> 5;
    int lane = threadIdx.x & 31;
    if (node >= NN) return;
    int beg = roff[node];
    int m = cnt[node];
    float adn = ad_[node];
    const float2* __restrict__ h2 = reinterpret_cast<const float2*>(h);
    float ax = 0.f, ay = 0.f, denom = 0.f;
    for (int base = 0; base < m; base += 32) {
        int rem = m - base;
        int nn = rem < 32 ? rem : 32;
        int s_l = 0;
        float ex_l = 0.f;
        if (lane < nn) {
            s_l = esrc[beg + base + lane];
            float e = as_[s_l] + adn;
            e = e > 0.f ? e : 0.2f * e;
            ex_l = __expf(e);
        }
        denom += ex_l;
#pragma unroll 4
        for (int j = 0; j < nn; ++j) {
            int s = __shfl_sync(0xffffffffu, s_l, j);
            float ex = __shfl_sync(0xffffffffu, ex_l, j);
            float2 hv = h2[(size_t)s * 32 + lane];
            ax += ex * hv.x;
            ay += ex * hv.y;
        }
    }
#pragma unroll
    for (int o = 16; o; o >>= 1) denom += __shfl_xor_sync(0xffffffffu, denom, o);
    float inv = 1.f / (denom + 1e-16f);
    float2 b2 = reinterpret_cast<const float2*>(bias)[lane];
    float2 g2 = reinterpret_cast<const float2*>(bg)[lane];
    float2 be2 = reinterpret_cast<const float2*>(bb)[lane];
    float2 m2 = reinterpret_cast<const float2*>(bm)[lane];
    float2 v2 = reinterpret_cast<const float2*>(bv)[lane];
    float vx = fmaxf(ax * inv + b2.x, 0.f);
    float vy = fmaxf(ay * inv + b2.y, 0.f);
    vx = (vx - m2.x) * rsqrtf(v2.x + 1e-5f) * g2.x + be2.x;
    vy = (vy - m2.y) * rsqrtf(v2.y + 1e-5f) * g2.y + be2.y;
    if (PROJ) {
        float2 p2 = reinterpret_cast<const float2*>(proj)[(size_t)node * 32 + lane];
        float2 pb2 = reinterpret_cast<const float2*>(projb)[lane];
        vx += p2.x + pb2.x;
        vy += p2.y + pb2.y;
    }
    reinterpret_cast<float2*>(out)[(size_t)node * 32 + lane] =
        make_float2(vx, vy);
}

// ---------------- mean pool ----------------
__global__ void zero_gsum(float* __restrict__ g) {
    if (threadIdx.x < HD) g[threadIdx.x] = 0.f;
}
__global__ void __launch_bounds__(256) pool(const float* __restrict__ xp,
                                            float* __restrict__ gsum) {
    int t = threadIdx.x;
    int c = t & 63;
    int row0 = blockIdx.x * 4 + (t >> 6);
    float acc = 0.f;
    for (int n = row0; n < NN; n += gridDim.x * 4) acc += xp[(size_t)n * HD + c];
    atomicAdd(&gsum[c], acc);
}

// ---------------- head MLP ----------------
__global__ void head(const float* __restrict__ gsum, const float* __restrict__ hW1,
                     const float* __restrict__ hb1, const float* __restrict__ hg,
                     const float* __restrict__ hb, const float* __restrict__ hm,
                     const float* __restrict__ hv, const float* __restrict__ hW2,
                     const float* __restrict__ hb2, float* __restrict__ out) {
    __shared__ float g[HD];
    int t = threadIdx.x;
    if (t < HD) g[t] = gsum[t] * (1.f / NN);
    __syncthreads();
    float r = 0.f;
    if (t < 32) {
        float acc = hb1[t];
#pragma unroll
        for (int k = 0; k < HD; k++) acc += g[k] * hW1[k * 32 + t];
        acc = fmaxf(acc, 0.f);
        acc = (acc - hm[t]) * rsqrtf(hv[t] + 1e-5f) * hg[t] + hb[t];
        r = acc * hW2[t];
#pragma unroll
        for (int o = 16; o; o >>= 1) r += __shfl_xor_sync(0xffffffffu, r, o);
        if (t == 0) out[0] = r + hb2[0];
    }
}

// ---------------- launch ----------------
extern "C" void kernel_launch(void* const* d_in, const int* in_sizes, int n_in,
                              void* d_out, int out_size) {
    (void)in_sizes; (void)n_in; (void)out_size;
    const float* x        = (const float*)d_in[0];
    const int*   ei       = (const int*)d_in[1];
    const float* conv1_W  = (const float*)d_in[2];
    const float* conv1_as = (const float*)d_in[3];
    const float* conv1_ad = (const float*)d_in[4];
    const float* conv1_b  = (const float*)d_in[5];
    const float* convW    = (const float*)d_in[6];
    const float* conv_as  = (const float*)d_in[7];
    const float* conv_ad  = (const float*)d_in[8];
    const float* conv_b   = (const float*)d_in[9];
    const float* bn_g     = (const float*)d_in[10];
    const float* bn_b     = (const float*)d_in[11];
    const float* bn_m     = (const float*)d_in[12];
    const float* bn_v     = (const float*)d_in[13];
    const float* projW    = (const float*)d_in[14];
    const float* projb    = (const float*)d_in[15];
    const float* hW1      = (const float*)d_in[16];
    const float* hb1      = (const float*)d_in[17];
    const float* hbn_g    = (const float*)d_in[18];
    const float* hbn_b    = (const float*)d_in[19];
    const float* hbn_m    = (const float*)d_in[20];
    const float* hbn_v    = (const float*)d_in[21];
    const float* hW2      = (const float*)d_in[22];
    const float* hb2      = (const float*)d_in[23];

    const int* src = ei;
    const int* dst = ei + EE;

    float *h, *x1, *x2, *proj, *as_, *ad_, *gsum;
    int *cnt, *roff, *fill, *bsum, *esrc;
    cudaGetSymbolAddress((void**)&h, d_h);
    cudaGetSymbolAddress((void**)&x1, d_x1);
    cudaGetSymbolAddress((void**)&x2, d_x2);
    cudaGetSymbolAddress((void**)&proj, d_proj);
    cudaGetSymbolAddress((void**)&as_, d_as);
    cudaGetSymbolAddress((void**)&ad_, d_ad);
    cudaGetSymbolAddress((void**)&gsum, d_gsum);
    cudaGetSymbolAddress((void**)&cnt, d_cnt);
    cudaGetSymbolAddress((void**)&roff, d_roff);
    cudaGetSymbolAddress((void**)&fill, d_fill);
    cudaGetSymbolAddress((void**)&bsum, d_bsum);
    cudaGetSymbolAddress((void**)&esrc, d_esrc);

    const int GB = (NN + 15) / 16;             // gemm blocks
    const int AB = (NN * 32 + 255) / 256;      // warp-per-node blocks (6250)
    const int NB = (NN + 255) / 256;           // node-sized blocks
    const int MB = (TOTE + 255) / 256;         // edge-sized blocks

    // ---- CSR build (per launch; edge_index constant) ----
    zero_cf<<<NB, 256>>>(cnt, fill);
    hist<<<MB, 256>>>(dst, cnt);
    scan1<<<NB_SCAN, 256>>>(cnt, roff, bsum);
    scan2<<<1, 256>>>(bsum);
    scan3<<<NB_SCAN, 256>>>(roff, bsum);
    scatter<<<MB, 256>>>(src, dst, roff, fill, esrc);

    // ---- layer 1 ----
    gemm16<IND><<<GB, 256>>>(x, conv1_W, h, conv1_as, conv1_ad, as_, ad_);
    agg_post<false><<<AB, 256>>>(roff, cnt, esrc, as_, ad_, h, conv1_b, bn_g,
                                 bn_b, bn_m, bn_v, nullptr, nullptr, x1);

    float* xp = x1;
    float* xn = x2;
    for (int l = 0; l < 4; l++) {
        gemm16<HD><<<GB, 256>>>(xp, convW + l * HD * HD, h, conv_as + l * HD,
                                conv_ad + l * HD, as_, ad_);
        gemm16<HD><<<GB, 256>>>(xp, projW + l * HD * HD, proj, nullptr, nullptr,
                                nullptr, nullptr);
        agg_post<true><<<AB, 256>>>(roff, cnt, esrc, as_, ad_, h,
                                    conv_b + l * HD, bn_g + (l + 1) * HD,
                                    bn_b + (l + 1) * HD, bn_m + (l + 1) * HD,
                                    bn_v + (l + 1) * HD, proj, projb + l * HD,
                                    xn);
        float* tmp = xp; xp = xn; xn = tmp;
    }

    zero_gsum<<<1, 64>>>(gsum);
    pool<<<256, 256>>>(xp, gsum);
    head<<<1, 64>>>(gsum, hW1, hb1, hbn_g, hbn_b, hbn_m, hbn_v, hW2, hb2,
                    (float*)d_out);
}

// round 7
// speedup vs baseline: 2.9853x; 1.3906x over previous
#include <cuda_runtime.h>

#define NN 50000
#define EE 800000
#define IND 128
#define HD 64
#define TOTE (EE + NN)
#define NB_SCAN 196   // ceil(NN/256)

// ---------------- scratch (static device memory; no allocations) ----------------
__device__ __align__(256) float d_h[NN * HD];
__device__ __align__(256) float d_x1[NN * HD];
__device__ __align__(256) float d_x2[NN * HD];
__device__ __align__(256) float d_proj[NN * HD];
__device__ __align__(256) float d_as[NN];
__device__ __align__(256) float d_ad[NN];
__device__ __align__(256) float d_gsum[HD];
__device__ __align__(256) int   d_cnt[NN];
__device__ __align__(256) int   d_roff[NN];
__device__ __align__(256) int   d_fill[NN];
__device__ __align__(256) int   d_bsum[NB_SCAN];
__device__ __align__(256) int   d_esrc[TOTE];

// ---------------- CSR build ----------------
__global__ void __launch_bounds__(256) zero_cf(int* __restrict__ cnt,
                                               int* __restrict__ fill) {
    int i = blockIdx.x * blockDim.x + threadIdx.x;
    if (i < NN) { cnt[i] = 0; fill[i] = 0; }
}

__global__ void __launch_bounds__(256) hist(const int* __restrict__ dst,
                                            int* __restrict__ cnt) {
    int i = blockIdx.x * blockDim.x + threadIdx.x;
    if (i >= TOTE) return;
    int d = (i < EE) ? dst[i] : (i - EE);
    atomicAdd(&cnt[d], 1);
}

__global__ void __launch_bounds__(256) scan1(const int* __restrict__ cnt,
                                             int* __restrict__ roff,
                                             int* __restrict__ bsum) {
    __shared__ int sh[256];
    int t = threadIdx.x;
    int i = blockIdx.x * 256 + t;
    int v = (i < NN) ? cnt[i] : 0;
    sh[t] = v;
    __syncthreads();
#pragma unroll
    for (int o = 1; o < 256; o <<= 1) {
        int u = (t >= o) ? sh[t - o] : 0;
        __syncthreads();
        sh[t] += u;
        __syncthreads();
    }
    if (i < NN) roff[i] = sh[t] - v;           // exclusive
    if (t == 255) bsum[blockIdx.x] = sh[255];  // block total
}

__global__ void __launch_bounds__(256) scan2(int* __restrict__ bsum) {
    __shared__ int sh[256];
    int t = threadIdx.x;
    int v = (t < NB_SCAN) ? bsum[t] : 0;
    sh[t] = v;
    __syncthreads();
#pragma unroll
    for (int o = 1; o < 256; o <<= 1) {
        int u = (t >= o) ? sh[t - o] : 0;
        __syncthreads();
        sh[t] += u;
        __syncthreads();
    }
    if (t < NB_SCAN) bsum[t] = sh[t] - v;      // exclusive over blocks
}

__global__ void __launch_bounds__(256) scan3(int* __restrict__ roff,
                                             const int* __restrict__ bsum) {
    int i = blockIdx.x * blockDim.x + threadIdx.x;
    if (i < NN) roff[i] += bsum[i >> 8];
}

__global__ void __launch_bounds__(256) scatter(const int* __restrict__ src,
                                               const int* __restrict__ dst,
                                               const int* __restrict__ roff,
                                               int* __restrict__ fill,
                                               int* __restrict__ esrc) {
    int i = blockIdx.x * blockDim.x + threadIdx.x;
    if (i >= TOTE) return;
    int s, d;
    if (i < EE) { s = src[i]; d = dst[i]; } else { s = d = i - EE; }
    int pos = roff[d] + atomicAdd(&fill[d], 1);
    esrc[pos] = s;
}

// ---------------- layer-1 GEMM (K=128) + fused scores ----------------
// 256 threads: cp = t&31 (col pair), g = t>>5 (8 groups x 2 rows) -> 16 rows/blk
__global__ void __launch_bounds__(256) gemm1(const float* __restrict__ X,
                                             const float* __restrict__ W,
                                             float* __restrict__ Y,
                                             const float* __restrict__ a_s,
                                             const float* __restrict__ a_d,
                                             float* __restrict__ as_o,
                                             float* __restrict__ ad_o) {
    __shared__ float Ws[IND * HD];   // 32KB
    __shared__ float Xs[16 * IND];   // 8KB
    int t = threadIdx.x;
    for (int i = t; i < IND * HD; i += 256) Ws[i] = W[i];
    int nb = blockIdx.x * 16;
    for (int i = t; i < 16 * IND; i += 256) {
        int r = i >> 7, c = i & 127;
        int node = nb + r;
        Xs[i] = (node < NN) ? X[(size_t)node * IND + c] : 0.f;
    }
    __syncthreads();
    int cp = t & 31, g = t >> 5;
    float2 a0 = make_float2(0.f, 0.f), a1 = make_float2(0.f, 0.f);
#pragma unroll 8
    for (int k = 0; k < IND; k++) {
        float2 w = reinterpret_cast<const float2*>(Ws)[k * 32 + cp];
        float x0 = Xs[(g * 2 + 0) * IND + k];
        float x1 = Xs[(g * 2 + 1) * IND + k];
        a0.x += x0 * w.x; a0.y += x0 * w.y;
        a1.x += x1 * w.x; a1.y += x1 * w.y;
    }
    int r0 = nb + g * 2;
    if (r0 < NN)
        reinterpret_cast<float2*>(Y)[(size_t)r0 * 32 + cp] = a0;
    if (r0 + 1 < NN)
        reinterpret_cast<float2*>(Y)[(size_t)(r0 + 1) * 32 + cp] = a1;
    float2 sv = reinterpret_cast<const float2*>(a_s)[cp];
    float2 dv = reinterpret_cast<const float2*>(a_d)[cp];
    float s0 = a0.x * sv.x + a0.y * sv.y;
    float s1 = a1.x * sv.x + a1.y * sv.y;
    float d0 = a0.x * dv.x + a0.y * dv.y;
    float d1 = a1.x * dv.x + a1.y * dv.y;
#pragma unroll
    for (int o = 16; o; o >>= 1) {
        s0 += __shfl_xor_sync(0xffffffffu, s0, o);
        s1 += __shfl_xor_sync(0xffffffffu, s1, o);
        d0 += __shfl_xor_sync(0xffffffffu, d0, o);
        d1 += __shfl_xor_sync(0xffffffffu, d1, o);
    }
    if ((t & 31) == 0) {
        if (r0 < NN) { as_o[r0] = s0; ad_o[r0] = d0; }
        if (r0 + 1 < NN) { as_o[r0 + 1] = s1; ad_o[r0 + 1] = d1; }
    }
}

// ---------------- dual GEMM (K=64): Y = X@Wc (+scores), P = X@Wp ----------
// 256 threads: cp = t&31 (col pair), g = t>>5 (8 groups x 4 rows) -> 32 rows/blk
__global__ void __launch_bounds__(256) gemm_dual(const float* __restrict__ X,
                                                 const float* __restrict__ Wc,
                                                 const float* __restrict__ Wp,
                                                 float* __restrict__ Y,
                                                 float* __restrict__ P,
                                                 const float* __restrict__ a_s,
                                                 const float* __restrict__ a_d,
                                                 float* __restrict__ as_o,
                                                 float* __restrict__ ad_o) {
    __shared__ float Wcs[HD * HD];  // 16KB
    __shared__ float Wps[HD * HD];  // 16KB
    __shared__ float Xs[32 * HD];   // 8KB
    int t = threadIdx.x;
    for (int i = t; i < HD * HD; i += 256) { Wcs[i] = Wc[i]; Wps[i] = Wp[i]; }
    int nb = blockIdx.x * 32;
    for (int i = t; i < 32 * HD; i += 256) {
        int r = i >> 6, c = i & 63;
        int node = nb + r;
        Xs[i] = (node < NN) ? X[(size_t)node * HD + c] : 0.f;
    }
    __syncthreads();
    int cp = t & 31, g = t >> 5;
    float2 c0 = make_float2(0.f, 0.f), c1 = c0, c2 = c0, c3 = c0;
    float2 p0 = c0, p1 = c0, p2 = c0, p3 = c0;
#pragma unroll 4
    for (int k = 0; k < HD; k++) {
        float2 wc = reinterpret_cast<const float2*>(Wcs)[k * 32 + cp];
        float2 wp = reinterpret_cast<const float2*>(Wps)[k * 32 + cp];
        float x0 = Xs[(g * 4 + 0) * HD + k];
        float x1 = Xs[(g * 4 + 1) * HD + k];
        float x2 = Xs[(g * 4 + 2) * HD + k];
        float x3 = Xs[(g * 4 + 3) * HD + k];
        c0.x += x0 * wc.x; c0.y += x0 * wc.y;
        c1.x += x1 * wc.x; c1.y += x1 * wc.y;
        c2.x += x2 * wc.x; c2.y += x2 * wc.y;
        c3.x += x3 * wc.x; c3.y += x3 * wc.y;
        p0.x += x0 * wp.x; p0.y += x0 * wp.y;
        p1.x += x1 * wp.x; p1.y += x1 * wp.y;
        p2.x += x2 * wp.x; p2.y += x2 * wp.y;
        p3.x += x3 * wp.x; p3.y += x3 * wp.y;
    }
    int r0 = nb + g * 4;
    float2* Y2 = reinterpret_cast<float2*>(Y);
    float2* P2 = reinterpret_cast<float2*>(P);
    if (r0 + 0 < NN) { Y2[(size_t)(r0 + 0) * 32 + cp] = c0; P2[(size_t)(r0 + 0) * 32 + cp] = p0; }
    if (r0 + 1 < NN) { Y2[(size_t)(r0 + 1) * 32 + cp] = c1; P2[(size_t)(r0 + 1) * 32 + cp] = p1; }
    if (r0 + 2 < NN) { Y2[(size_t)(r0 + 2) * 32 + cp] = c2; P2[(size_t)(r0 + 2) * 32 + cp] = p2; }
    if (r0 + 3 < NN) { Y2[(size_t)(r0 + 3) * 32 + cp] = c3; P2[(size_t)(r0 + 3) * 32 + cp] = p3; }
    float2 sv = reinterpret_cast<const float2*>(a_s)[cp];
    float2 dv = reinterpret_cast<const float2*>(a_d)[cp];
    float s0 = c0.x * sv.x + c0.y * sv.y;
    float s1 = c1.x * sv.x + c1.y * sv.y;
    float s2 = c2.x * sv.x + c2.y * sv.y;
    float s3 = c3.x * sv.x + c3.y * sv.y;
    float d0 = c0.x * dv.x + c0.y * dv.y;
    float d1 = c1.x * dv.x + c1.y * dv.y;
    float d2 = c2.x * dv.x + c2.y * dv.y;
    float d3 = c3.x * dv.x + c3.y * dv.y;
#pragma unroll
    for (int o = 16; o; o >>= 1) {
        s0 += __shfl_xor_sync(0xffffffffu, s0, o);
        s1 += __shfl_xor_sync(0xffffffffu, s1, o);
        s2 += __shfl_xor_sync(0xffffffffu, s2, o);
        s3 += __shfl_xor_sync(0xffffffffu, s3, o);
        d0 += __shfl_xor_sync(0xffffffffu, d0, o);
        d1 += __shfl_xor_sync(0xffffffffu, d1, o);
        d2 += __shfl_xor_sync(0xffffffffu, d2, o);
        d3 += __shfl_xor_sync(0xffffffffu, d3, o);
    }
    if ((t & 31) == 0) {
        if (r0 + 0 < NN) { as_o[r0 + 0] = s0; ad_o[r0 + 0] = d0; }
        if (r0 + 1 < NN) { as_o[r0 + 1] = s1; ad_o[r0 + 1] = d1; }
        if (r0 + 2 < NN) { as_o[r0 + 2] = s2; ad_o[r0 + 2] = d2; }
        if (r0 + 3 < NN) { as_o[r0 + 3] = s3; ad_o[r0 + 3] = d3; }
    }
}

// ---------------- fused gather-aggregate + softmax + bias/relu/bn(+proj) ------
// One warp per destination node. Half-warps process 2 edges concurrently;
// within a half, lane q (0..15) covers cols [4q, 4q+3] (float4).
template <bool PROJ>
__global__ void __launch_bounds__(256) agg_post(
    const int* __restrict__ roff, const int* __restrict__ cnt,
    const int* __restrict__ esrc, const float* __restrict__ as_,
    const float* __restrict__ ad_, const float* __restrict__ h,
    const float* __restrict__ bias, const float* __restrict__ bg,
    const float* __restrict__ bb, const float* __restrict__ bm,
    const float* __restrict__ bv, const float* __restrict__ proj,
    const float* __restrict__ projb, float* __restrict__ out) {
    int node = (blockIdx.x * blockDim.x + threadIdx.x) >> 5;
    int lane = threadIdx.x & 31;
    if (node >= NN) return;
    int beg = roff[node];
    int m = cnt[node];
    float adn = ad_[node];
    const float4* __restrict__ h4 = reinterpret_cast<const float4*>(h);
    int q = lane & 15, half = lane >> 4;
    float ax = 0.f, ay = 0.f, az = 0.f, aw = 0.f, denom = 0.f;
    for (int base = 0; base < m; base += 32) {
        int rem = m - base;
        int nn = rem < 32 ? rem : 32;
        int s_l = 0;
        float ex_l = 0.f;
        if (lane < nn) {
            s_l = esrc[beg + base + lane];
            float e = as_[s_l] + adn;
            e = e > 0.f ? e : 0.2f * e;
            ex_l = __expf(e);
        }
        denom += ex_l;
#pragma unroll 2
        for (int j = 0; j < nn; j += 2) {
            int jj = j + half;
            int s = __shfl_sync(0xffffffffu, s_l, jj & 31);
            float ex = __shfl_sync(0xffffffffu, ex_l, jj & 31);
            if (jj < nn) {
                float4 hv = h4[(size_t)s * 16 + q];
                ax += ex * hv.x;
                ay += ex * hv.y;
                az += ex * hv.z;
                aw += ex * hv.w;
            }
        }
    }
    // merge the two edge-halves (same columns, disjoint edge subsets)
    ax += __shfl_xor_sync(0xffffffffu, ax, 16);
    ay += __shfl_xor_sync(0xffffffffu, ay, 16);
    az += __shfl_xor_sync(0xffffffffu, az, 16);
    aw += __shfl_xor_sync(0xffffffffu, aw, 16);
#pragma unroll
    for (int o = 16; o; o >>= 1) denom += __shfl_xor_sync(0xffffffffu, denom, o);
    if (half == 0) {
        float inv = 1.f / (denom + 1e-16f);
        float4 b4 = reinterpret_cast<const float4*>(bias)[q];
        float4 g4 = reinterpret_cast<const float4*>(bg)[q];
        float4 be4 = reinterpret_cast<const float4*>(bb)[q];
        float4 m4 = reinterpret_cast<const float4*>(bm)[q];
        float4 v4 = reinterpret_cast<const float4*>(bv)[q];
        float vx = fmaxf(ax * inv + b4.x, 0.f);
        float vy = fmaxf(ay * inv + b4.y, 0.f);
        float vz = fmaxf(az * inv + b4.z, 0.f);
        float vw = fmaxf(aw * inv + b4.w, 0.f);
        vx = (vx - m4.x) * rsqrtf(v4.x + 1e-5f) * g4.x + be4.x;
        vy = (vy - m4.y) * rsqrtf(v4.y + 1e-5f) * g4.y + be4.y;
        vz = (vz - m4.z) * rsqrtf(v4.z + 1e-5f) * g4.z + be4.z;
        vw = (vw - m4.w) * rsqrtf(v4.w + 1e-5f) * g4.w + be4.w;
        if (PROJ) {
            float4 p4 = reinterpret_cast<const float4*>(proj)[(size_t)node * 16 + q];
            float4 pb4 = reinterpret_cast<const float4*>(projb)[q];
            vx += p4.x + pb4.x;
            vy += p4.y + pb4.y;
            vz += p4.z + pb4.z;
            vw += p4.w + pb4.w;
        }
        reinterpret_cast<float4*>(out)[(size_t)node * 16 + q] =
            make_float4(vx, vy, vz, vw);
    }
}

// ---------------- mean pool ----------------
__global__ void zero_gsum(float* __restrict__ g) {
    if (threadIdx.x < HD) g[threadIdx.x] = 0.f;
}
__global__ void __launch_bounds__(256) pool(const float* __restrict__ xp,
                                            float* __restrict__ gsum) {
    int t = threadIdx.x;
    int c = t & 63;
    int row0 = blockIdx.x * 4 + (t >> 6);
    float acc = 0.f;
    for (int n = row0; n < NN; n += gridDim.x * 4) acc += xp[(size_t)n * HD + c];
    atomicAdd(&gsum[c], acc);
}

// ---------------- head MLP ----------------
__global__ void head(const float* __restrict__ gsum, const float* __restrict__ hW1,
                     const float* __restrict__ hb1, const float* __restrict__ hg,
                     const float* __restrict__ hb, const float* __restrict__ hm,
                     const float* __restrict__ hv, const float* __restrict__ hW2,
                     const float* __restrict__ hb2, float* __restrict__ out) {
    __shared__ float g[HD];
    int t = threadIdx.x;
    if (t < HD) g[t] = gsum[t] * (1.f / NN);
    __syncthreads();
    float r = 0.f;
    if (t < 32) {
        float acc = hb1[t];
#pragma unroll
        for (int k = 0; k < HD; k++) acc += g[k] * hW1[k * 32 + t];
        acc = fmaxf(acc, 0.f);
        acc = (acc - hm[t]) * rsqrtf(hv[t] + 1e-5f) * hg[t] + hb[t];
        r = acc * hW2[t];
#pragma unroll
        for (int o = 16; o; o >>= 1) r += __shfl_xor_sync(0xffffffffu, r, o);
        if (t == 0) out[0] = r + hb2[0];
    }
}

// ---------------- launch ----------------
extern "C" void kernel_launch(void* const* d_in, const int* in_sizes, int n_in,
                              void* d_out, int out_size) {
    (void)in_sizes; (void)n_in; (void)out_size;
    const float* x        = (const float*)d_in[0];
    const int*   ei       = (const int*)d_in[1];
    const float* conv1_W  = (const float*)d_in[2];
    const float* conv1_as = (const float*)d_in[3];
    const float* conv1_ad = (const float*)d_in[4];
    const float* conv1_b  = (const float*)d_in[5];
    const float* convW    = (const float*)d_in[6];
    const float* conv_as  = (const float*)d_in[7];
    const float* conv_ad  = (const float*)d_in[8];
    const float* conv_b   = (const float*)d_in[9];
    const float* bn_g     = (const float*)d_in[10];
    const float* bn_b     = (const float*)d_in[11];
    const float* bn_m     = (const float*)d_in[12];
    const float* bn_v     = (const float*)d_in[13];
    const float* projW    = (const float*)d_in[14];
    const float* projb    = (const float*)d_in[15];
    const float* hW1      = (const float*)d_in[16];
    const float* hb1      = (const float*)d_in[17];
    const float* hbn_g    = (const float*)d_in[18];
    const float* hbn_b    = (const float*)d_in[19];
    const float* hbn_m    = (const float*)d_in[20];
    const float* hbn_v    = (const float*)d_in[21];
    const float* hW2      = (const float*)d_in[22];
    const float* hb2      = (const float*)d_in[23];

    const int* src = ei;
    const int* dst = ei + EE;

    float *h, *x1, *x2, *proj, *as_, *ad_, *gsum;
    int *cnt, *roff, *fill, *bsum, *esrc;
    cudaGetSymbolAddress((void**)&h, d_h);
    cudaGetSymbolAddress((void**)&x1, d_x1);
    cudaGetSymbolAddress((void**)&x2, d_x2);
    cudaGetSymbolAddress((void**)&proj, d_proj);
    cudaGetSymbolAddress((void**)&as_, d_as);
    cudaGetSymbolAddress((void**)&ad_, d_ad);
    cudaGetSymbolAddress((void**)&gsum, d_gsum);
    cudaGetSymbolAddress((void**)&cnt, d_cnt);
    cudaGetSymbolAddress((void**)&roff, d_roff);
    cudaGetSymbolAddress((void**)&fill, d_fill);
    cudaGetSymbolAddress((void**)&bsum, d_bsum);
    cudaGetSymbolAddress((void**)&esrc, d_esrc);

    const int G1 = (NN + 15) / 16;             // gemm1 blocks (16 rows)
    const int GD = (NN + 31) / 32;             // gemm_dual blocks (32 rows)
    const int AB = (NN * 32 + 255) / 256;      // warp-per-node blocks
    const int NB = (NN + 255) / 256;           // node-sized blocks
    const int MB = (TOTE + 255) / 256;         // edge-sized blocks

    // ---- CSR build (per launch; edge_index constant) ----
    zero_cf<<<NB, 256>>>(cnt, fill);
    hist<<<MB, 256>>>(dst, cnt);
    scan1<<<NB_SCAN, 256>>>(cnt, roff, bsum);
    scan2<<<1, 256>>>(bsum);
    scan3<<<NB_SCAN, 256>>>(roff, bsum);
    scatter<<<MB, 256>>>(src, dst, roff, fill, esrc);

    // ---- layer 1 ----
    gemm1<<<G1, 256>>>(x, conv1_W, h, conv1_as, conv1_ad, as_, ad_);
    agg_post<false><<<AB, 256>>>(roff, cnt, esrc, as_, ad_, h, conv1_b, bn_g,
                                 bn_b, bn_m, bn_v, nullptr, nullptr, x1);

    float* xp = x1;
    float* xn = x2;
    for (int l = 0; l < 4; l++) {
        gemm_dual<<<GD, 256>>>(xp, convW + l * HD * HD, projW + l * HD * HD, h,
                               proj, conv_as + l * HD, conv_ad + l * HD, as_,
                               ad_);
        agg_post<true><<<AB, 256>>>(roff, cnt, esrc, as_, ad_, h,
                                    conv_b + l * HD, bn_g + (l + 1) * HD,
                                    bn_b + (l + 1) * HD, bn_m + (l + 1) * HD,
                                    bn_v + (l + 1) * HD, proj, projb + l * HD,
                                    xn);
        float* tmp = xp; xp = xn; xn = tmp;
    }

    zero_gsum<<<1, 64>>>(gsum);
    pool<<<256, 256>>>(xp, gsum);
    head<<<1, 64>>>(gsum, hW1, hb1, hbn_g, hbn_b, hbn_m, hbn_v, hW2, hb2,
                    (float*)d_out);
}